// round 1
// baseline (speedup 1.0000x reference)
#include <cuda_runtime.h>
#include <math.h>
#include <stdint.h>

#define NROWS 8192          // 32*16*16 samples
#define KC    8192          // codebook size
#define DD    256           // feature dim
#define TOTAL_Q (NROWS*DD)  // 2097152
#define INV_T 100.0f        // 1/ENTROPY_TEMPERATURE

// -------- scratch (device globals: no allocations allowed) --------
__device__ float g_G[(size_t)NROWS * KC];   // 256 MB: G[n,k] = x_n . c_k
__device__ float g_c2[KC];                  // |c_k|^2
__device__ float g_m[NROWS];                // row max logit (shifted)
__device__ float g_sinv[NROWS];             // 1 / sum exp
__device__ int   g_idx[NROWS];              // argmin index
__device__ float g_avgp[KC];                // sum_n p[n,k]
__device__ float g_plogp;                   // sum_n (u/s - log s)
__device__ float g_avgent;                  // avg entropy (positive)
__device__ float g_mse;                     // sum (q-x)^2

// -------- init: zero accumulators (graph-replay safe) --------
__global__ void init_kernel() {
    int i = blockIdx.x * blockDim.x + threadIdx.x;
    if (i < KC) g_avgp[i] = 0.f;
    if (i == 0) { g_plogp = 0.f; g_avgent = 0.f; g_mse = 0.f; }
}

// -------- |c_k|^2 --------
__global__ __launch_bounds__(256) void c2_kernel(const float* __restrict__ cb) {
    int k = blockIdx.x;
    float v = cb[(size_t)k * DD + threadIdx.x];
    float sq = v * v;
    #pragma unroll
    for (int o = 16; o; o >>= 1) sq += __shfl_down_sync(0xffffffff, sq, o);
    __shared__ float sh[8];
    int wid = threadIdx.x >> 5, lid = threadIdx.x & 31;
    if (lid == 0) sh[wid] = sq;
    __syncthreads();
    if (threadIdx.x == 0) {
        float t = 0.f;
        #pragma unroll
        for (int w = 0; w < 8; w++) t += sh[w];
        g_c2[k] = t;
    }
}

// -------- fp32 SGEMM: G = X (N x D) * C^T (D x K) --------
// 128x128 block tile, BK=16, 256 threads, 8x8 per thread.
__global__ __launch_bounds__(256, 2) void gemm_kernel(const float* __restrict__ A,
                                                      const float* __restrict__ B) {
    __shared__ float As[16][128];
    __shared__ float Bs[16][128];
    int tid = threadIdx.x;
    int tx = tid & 15, ty = tid >> 4;
    int row0 = blockIdx.y * 128, col0 = blockIdx.x * 128;
    int lr = tid >> 2;            // 0..63
    int lc = (tid & 3) * 4;       // 0,4,8,12
    const float* Aptr = A + (size_t)(row0 + lr) * DD + lc;
    const float* Bptr = B + (size_t)(col0 + lr) * DD + lc;

    float acc[8][8];
    #pragma unroll
    for (int i = 0; i < 8; i++)
        #pragma unroll
        for (int j = 0; j < 8; j++) acc[i][j] = 0.f;

    for (int d0 = 0; d0 < DD; d0 += 16) {
        float4 a0 = *(const float4*)(Aptr + d0);
        float4 a1 = *(const float4*)(Aptr + (size_t)64 * DD + d0);
        float4 b0 = *(const float4*)(Bptr + d0);
        float4 b1 = *(const float4*)(Bptr + (size_t)64 * DD + d0);
        __syncthreads();
        As[lc + 0][lr] = a0.x; As[lc + 1][lr] = a0.y; As[lc + 2][lr] = a0.z; As[lc + 3][lr] = a0.w;
        As[lc + 0][lr + 64] = a1.x; As[lc + 1][lr + 64] = a1.y; As[lc + 2][lr + 64] = a1.z; As[lc + 3][lr + 64] = a1.w;
        Bs[lc + 0][lr] = b0.x; Bs[lc + 1][lr] = b0.y; Bs[lc + 2][lr] = b0.z; Bs[lc + 3][lr] = b0.w;
        Bs[lc + 0][lr + 64] = b1.x; Bs[lc + 1][lr + 64] = b1.y; Bs[lc + 2][lr + 64] = b1.z; Bs[lc + 3][lr + 64] = b1.w;
        __syncthreads();
        #pragma unroll
        for (int kk = 0; kk < 16; kk++) {
            float ra[8], rb[8];
            #pragma unroll
            for (int i = 0; i < 8; i++) ra[i] = As[kk][ty * 8 + i];
            #pragma unroll
            for (int j = 0; j < 8; j++) rb[j] = Bs[kk][tx * 8 + j];
            #pragma unroll
            for (int i = 0; i < 8; i++)
                #pragma unroll
                for (int j = 0; j < 8; j++)
                    acc[i][j] += ra[i] * rb[j];
        }
    }
    #pragma unroll
    for (int i = 0; i < 8; i++) {
        size_t off = (size_t)(row0 + ty * 8 + i) * KC + col0 + tx * 8;
        float4 v0 = make_float4(acc[i][0], acc[i][1], acc[i][2], acc[i][3]);
        float4 v1 = make_float4(acc[i][4], acc[i][5], acc[i][6], acc[i][7]);
        *(float4*)&g_G[off]     = v0;
        *(float4*)&g_G[off + 4] = v1;
    }
}

// -------- per-row stats: argmax logit (first-index tie), s, u --------
// logit' l = (2G - |c|^2) / T   (drops the -|x|^2/T constant: softmax-invariant)
__global__ __launch_bounds__(256) void rowstats_kernel() {
    __shared__ float sl[KC];        // 32 KB: row of shifted logits
    __shared__ float sval[256];
    __shared__ int   sidx[256];
    __shared__ float ss[256], su[256];
    int n = blockIdx.x, tid = threadIdx.x;
    const float* Grow = g_G + (size_t)n * KC;

    float best = -INFINITY; int bidx = KC;
    for (int k = tid; k < KC; k += 256) {
        float l = (2.f * Grow[k] - g_c2[k]) * INV_T;
        sl[k] = l;
        if (l > best) { best = l; bidx = k; }   // strict > keeps first occurrence
    }
    sval[tid] = best; sidx[tid] = bidx;
    __syncthreads();
    for (int off = 128; off; off >>= 1) {
        if (tid < off) {
            float ov = sval[tid + off]; int oi = sidx[tid + off];
            if (ov > sval[tid] || (ov == sval[tid] && oi < sidx[tid])) { sval[tid] = ov; sidx[tid] = oi; }
        }
        __syncthreads();
    }
    float m = sval[0]; int idx = sidx[0];

    float s = 0.f, u = 0.f;
    for (int k = tid; k < KC; k += 256) {
        float z = sl[k] - m;
        float e = __expf(z);
        s += e; u += z * e;
    }
    ss[tid] = s; su[tid] = u;
    __syncthreads();
    for (int off = 128; off; off >>= 1) {
        if (tid < off) { ss[tid] += ss[tid + off]; su[tid] += su[tid + off]; }
        __syncthreads();
    }
    if (tid == 0) {
        float S = ss[0], U = su[0];
        g_m[n] = m; g_sinv[n] = 1.f / S; g_idx[n] = idx;
        atomicAdd(&g_plogp, U / S - logf(S));   // row sum p*logp
    }
}

// -------- avg_probs accumulation: column pass over G --------
// grid (32, 8): 256-column chunks x 1024-row chunks
__global__ __launch_bounds__(256) void avgp_kernel() {
    __shared__ float sm_m[256], sm_si[256];
    int c = blockIdx.x * 256 + threadIdx.x;
    int n0 = blockIdx.y * (NROWS / 8);
    float c2c = g_c2[c];
    float acc = 0.f;
    for (int base = n0; base < n0 + NROWS / 8; base += 256) {
        __syncthreads();
        sm_m[threadIdx.x]  = g_m[base + threadIdx.x];
        sm_si[threadIdx.x] = g_sinv[base + threadIdx.x];
        __syncthreads();
        #pragma unroll 4
        for (int j = 0; j < 256; j++) {
            size_t n = (size_t)(base + j);
            float l = (2.f * g_G[n * KC + c] - c2c) * INV_T;
            acc += __expf(l - sm_m[j]) * sm_si[j];
        }
    }
    atomicAdd(&g_avgp[c], acc);
}

// -------- avg entropy: -sum avg_p * log(avg_p + eps) --------
__global__ __launch_bounds__(256) void avgent_kernel() {
    int i = blockIdx.x * blockDim.x + threadIdx.x;
    float ap = g_avgp[i] * (1.f / (float)NROWS);
    float h = -ap * logf(ap + 1e-5f);
    #pragma unroll
    for (int o = 16; o; o >>= 1) h += __shfl_down_sync(0xffffffff, h, o);
    __shared__ float sh[8];
    int wid = threadIdx.x >> 5, lid = threadIdx.x & 31;
    if (lid == 0) sh[wid] = h;
    __syncthreads();
    if (threadIdx.x == 0) {
        float t = 0.f;
        #pragma unroll
        for (int w = 0; w < 8; w++) t += sh[w];
        atomicAdd(&g_avgent, t);
    }
}

// -------- gather quantized rows + MSE + index output --------
__global__ __launch_bounds__(256) void gather_kernel(const float* __restrict__ x,
                                                     const float* __restrict__ cb,
                                                     float* __restrict__ out) {
    int n = blockIdx.x, tid = threadIdx.x;
    int idx = g_idx[n];
    float q  = cb[(size_t)idx * DD + tid];
    float xv = x[(size_t)n * DD + tid];
    out[(size_t)n * DD + tid] = q;       // quantized_st == quantized numerically
    float d = q - xv;
    float sq = d * d;
    #pragma unroll
    for (int o = 16; o; o >>= 1) sq += __shfl_down_sync(0xffffffff, sq, o);
    __shared__ float sh[8];
    int wid = tid >> 5, lid = tid & 31;
    if (lid == 0) sh[wid] = sq;
    __syncthreads();
    if (tid == 0) {
        float t = 0.f;
        #pragma unroll
        for (int w = 0; w < 8; w++) t += sh[w];
        atomicAdd(&g_mse, t);
        out[(size_t)TOTAL_Q + 1 + n] = (float)idx;   // indices after loss scalar
    }
}

// -------- final scalar loss --------
__global__ void final_kernel(float* __restrict__ out) {
    float mse_mean = g_mse / (float)TOTAL_Q;
    float sample_entropy = -g_plogp / (float)NROWS;
    float entropy_loss = sample_entropy - g_avgent;
    float loss = 1.25f * mse_mean + 0.1f * entropy_loss;  // (0.25 + 1.0)*mse + 0.1*ent
    out[TOTAL_Q] = loss;
}

extern "C" void kernel_launch(void* const* d_in, const int* in_sizes, int n_in,
                              void* d_out, int out_size) {
    const float* x  = (const float*)d_in[0];   // (32,16,16,256) fp32
    const float* cb = (const float*)d_in[1];   // (8192,256) fp32
    float* out = (float*)d_out;                // [quantized | loss | indices]

    init_kernel<<<32, 256>>>();
    c2_kernel<<<KC, 256>>>(cb);
    gemm_kernel<<<dim3(KC / 128, NROWS / 128), 256>>>(x, cb);
    rowstats_kernel<<<NROWS, 256>>>();
    avgp_kernel<<<dim3(KC / 256, 8), 256>>>();
    avgent_kernel<<<KC / 256, 256>>>();
    gather_kernel<<<NROWS, 256>>>(x, cb, out);
    final_kernel<<<1, 1>>>(out);
}

// round 3
// speedup vs baseline: 1.0073x; 1.0073x over previous
#include <cuda_runtime.h>
#include <cuda_bf16.h>
#include <math.h>
#include <stdint.h>

#define NROWS 8192
#define KC    8192
#define DD    256
#define TOTAL_Q (NROWS*DD)
#define INV_T 100.0f
#define KBIG  768

// ---------------- scratch ----------------
__device__ float g_G[(size_t)NROWS * KC];            // 256 MB
__device__ __nv_bfloat16 g_Abig[(size_t)NROWS * KBIG];
__device__ __nv_bfloat16 g_Bbig[(size_t)KC * KBIG];
__device__ float g_c2[KC];
__device__ int   g_idx[NROWS];
__device__ float g_avgp[KC];
__device__ int   g_flag[NROWS];
__device__ int   g_nflag;
__device__ float g_plogp;
__device__ float g_avgent;
__device__ float g_mse;

// ---------------- init ----------------
__global__ void init_kernel() {
    int i = blockIdx.x * blockDim.x + threadIdx.x;
    if (i < KC) g_avgp[i] = 0.f;
    if (i == 0) { g_plogp = 0.f; g_avgent = 0.f; g_mse = 0.f; g_nflag = 0; }
}

// ---------------- |c_k|^2 ----------------
__global__ __launch_bounds__(256) void c2_kernel(const float* __restrict__ cb) {
    int k = blockIdx.x;
    float v = cb[(size_t)k * DD + threadIdx.x];
    float sq = v * v;
    #pragma unroll
    for (int o = 16; o; o >>= 1) sq += __shfl_down_sync(0xffffffff, sq, o);
    __shared__ float sh[8];
    int wid = threadIdx.x >> 5, lid = threadIdx.x & 31;
    if (lid == 0) sh[wid] = sq;
    __syncthreads();
    if (threadIdx.x == 0) {
        float t = 0.f;
        #pragma unroll
        for (int w = 0; w < 8; w++) t += sh[w];
        g_c2[k] = t;
    }
}

// ---------------- split fp32 -> bf16 hi/lo (vectorized) ----------------
__device__ __forceinline__ uint32_t pack2(float a, float b) {
    __nv_bfloat162 t = __floats2bfloat162_rn(a, b);
    return reinterpret_cast<uint32_t&>(t);
}
__global__ __launch_bounds__(256) void convert_kernel(const float* __restrict__ x,
                                                      const float* __restrict__ cb) {
    int i = (blockIdx.x * 256 + threadIdx.x) * 4;    // 0..2M-1 step 4
    int n = i >> 8, d = i & 255;
    {
        float4 v = *(const float4*)(x + i);
        float hx = __bfloat162float(__float2bfloat16(v.x));
        float hy = __bfloat162float(__float2bfloat16(v.y));
        float hz = __bfloat162float(__float2bfloat16(v.z));
        float hw = __bfloat162float(__float2bfloat16(v.w));
        uint2 hi = make_uint2(pack2(hx, hy), pack2(hz, hw));
        uint2 lo = make_uint2(pack2(v.x - hx, v.y - hy), pack2(v.z - hz, v.w - hw));
        size_t b = (size_t)n * KBIG + d;
        *(uint2*)(g_Abig + b)       = hi;
        *(uint2*)(g_Abig + b + 256) = hi;
        *(uint2*)(g_Abig + b + 512) = lo;
    }
    {
        float4 v = *(const float4*)(cb + i);
        float hx = __bfloat162float(__float2bfloat16(v.x));
        float hy = __bfloat162float(__float2bfloat16(v.y));
        float hz = __bfloat162float(__float2bfloat16(v.z));
        float hw = __bfloat162float(__float2bfloat16(v.w));
        uint2 hi = make_uint2(pack2(hx, hy), pack2(hz, hw));
        uint2 lo = make_uint2(pack2(v.x - hx, v.y - hy), pack2(v.z - hz, v.w - hw));
        size_t b = (size_t)n * KBIG + d;
        *(uint2*)(g_Bbig + b)       = hi;
        *(uint2*)(g_Bbig + b + 256) = lo;
        *(uint2*)(g_Bbig + b + 512) = hi;
    }
}

// ---------------- bf16 mma.sync GEMM: G = Abig * Bbig^T ----------------
// 128x128 CTA tile, BK=32, 8 warps of 32x64, cp.async double buffer.
#define BM 128
#define BN 128
#define BK 32
#define PAD 40                 // smem row stride in bf16 elems
#define TILE_E (128*PAD)       // 5120 elems per tile
#define TILE_B (TILE_E*2)      // 10240 bytes
#define STAGE_B (TILE_B*2)     // 20480 bytes per stage (A+B)
#define NIT (KBIG/BK)          // 24

__device__ __forceinline__ void mma16816(float* d, const uint32_t* a, const uint32_t* b) {
    asm volatile("mma.sync.aligned.m16n8k16.row.col.f32.bf16.bf16.f32 "
        "{%0,%1,%2,%3}, {%4,%5,%6,%7}, {%8,%9}, {%0,%1,%2,%3};"
        : "+f"(d[0]), "+f"(d[1]), "+f"(d[2]), "+f"(d[3])
        : "r"(a[0]), "r"(a[1]), "r"(a[2]), "r"(a[3]), "r"(b[0]), "r"(b[1]));
}
__device__ __forceinline__ void ldsm4(uint32_t* r, uint32_t addr) {
    asm volatile("ldmatrix.sync.aligned.m8n8.x4.shared.b16 {%0,%1,%2,%3}, [%4];"
        : "=r"(r[0]), "=r"(r[1]), "=r"(r[2]), "=r"(r[3]) : "r"(addr));
}

__global__ __launch_bounds__(256) void mma_gemm_kernel() {
    __shared__ __align__(16) __nv_bfloat16 smem[2 * 2 * TILE_E];
    int tid = threadIdx.x, lane = tid & 31, wid = tid >> 5;
    int warpM = wid & 3, warpN = wid >> 2;
    int row0 = blockIdx.y * BM, col0 = blockIdx.x * BN;

    const __nv_bfloat16* Ag = g_Abig + (size_t)row0 * KBIG;
    const __nv_bfloat16* Bg = g_Bbig + (size_t)col0 * KBIG;
    uint32_t sbase = (uint32_t)__cvta_generic_to_shared(smem);

    // loader: 512 16B chunks per tile; each thread does 2 for A, 2 for B
    int lr0 = (tid + 0)   >> 2, ls0 = (tid + 0)   & 3;
    int lr1 = (tid + 256) >> 2, ls1 = (tid + 256) & 3;
    uint32_t so0 = (uint32_t)(lr0 * PAD + ls0 * 8) * 2;
    uint32_t so1 = (uint32_t)(lr1 * PAD + ls1 * 8) * 2;

    #define LOAD_STAGE(stage, kc) do { \
        uint32_t abase = sbase + (stage) * STAGE_B; \
        uint32_t bbase = abase + TILE_B; \
        asm volatile("cp.async.ca.shared.global [%0], [%1], 16;" :: "r"(abase + so0), "l"(Ag + (size_t)lr0 * KBIG + (kc) + ls0 * 8)); \
        asm volatile("cp.async.ca.shared.global [%0], [%1], 16;" :: "r"(abase + so1), "l"(Ag + (size_t)lr1 * KBIG + (kc) + ls1 * 8)); \
        asm volatile("cp.async.ca.shared.global [%0], [%1], 16;" :: "r"(bbase + so0), "l"(Bg + (size_t)lr0 * KBIG + (kc) + ls0 * 8)); \
        asm volatile("cp.async.ca.shared.global [%0], [%1], 16;" :: "r"(bbase + so1), "l"(Bg + (size_t)lr1 * KBIG + (kc) + ls1 * 8)); \
        asm volatile("cp.async.commit_group;"); \
    } while (0)

    // ldmatrix per-lane offsets
    int lrow = ((lane >> 3) & 1) * 8 + (lane & 7);
    int lkof = (lane >> 4) * 8;
    uint32_t aoff = (uint32_t)((warpM * 32 + lrow) * PAD + lkof) * 2;
    uint32_t boff = (uint32_t)((warpN * 64 + lrow) * PAD + lkof) * 2;

    float acc[2][8][4];
    #pragma unroll
    for (int mt = 0; mt < 2; mt++)
        #pragma unroll
        for (int nt = 0; nt < 8; nt++)
            #pragma unroll
            for (int j = 0; j < 4; j++) acc[mt][nt][j] = 0.f;

    LOAD_STAGE(0, 0);

    for (int it = 0; it < NIT; it++) {
        if (it + 1 < NIT) {
            LOAD_STAGE((it + 1) & 1, (it + 1) * BK);
            asm volatile("cp.async.wait_group 1;");
        } else {
            asm volatile("cp.async.wait_group 0;");
        }
        __syncthreads();

        uint32_t bufA = sbase + (it & 1) * STAGE_B;
        uint32_t bufB = bufA + TILE_B;
        #pragma unroll
        for (int ks = 0; ks < 2; ks++) {
            uint32_t kst = ks * 16 * 2;
            uint32_t aF[2][4];
            #pragma unroll
            for (int mt = 0; mt < 2; mt++)
                ldsm4(aF[mt], bufA + aoff + mt * (16 * PAD * 2) + kst);
            uint32_t bF[8][2];
            #pragma unroll
            for (int p = 0; p < 4; p++) {
                uint32_t r[4];
                ldsm4(r, bufB + boff + p * (16 * PAD * 2) + kst);
                bF[2*p][0] = r[0]; bF[2*p][1] = r[2];
                bF[2*p+1][0] = r[1]; bF[2*p+1][1] = r[3];
            }
            #pragma unroll
            for (int mt = 0; mt < 2; mt++)
                #pragma unroll
                for (int nt = 0; nt < 8; nt++)
                    mma16816(acc[mt][nt], aF[mt], bF[nt]);
        }
        __syncthreads();
    }

    // epilogue: d0,d1 -> row l/4; d2,d3 -> row l/4+8; cols 2*(l%4)
    int mr = row0 + warpM * 32 + (lane >> 2);
    int nc = col0 + warpN * 64 + (lane & 3) * 2;
    #pragma unroll
    for (int mt = 0; mt < 2; mt++) {
        #pragma unroll
        for (int nt = 0; nt < 8; nt++) {
            float* d = acc[mt][nt];
            size_t o0 = (size_t)(mr + mt * 16) * KC + nc + nt * 8;
            size_t o1 = (size_t)(mr + mt * 16 + 8) * KC + nc + nt * 8;
            *(float2*)(g_G + o0) = make_float2(d[0], d[1]);
            *(float2*)(g_G + o1) = make_float2(d[2], d[3]);
        }
    }
}

// ---------------- fused row stats + avg_probs partials ----------------
// one block per 32 rows; row logits and avgp partials live in smem
__global__ __launch_bounds__(256) void rowstats_kernel() {
    extern __shared__ float dynsm[];
    float* sl = dynsm;            // 8192: current row logits
    float* ap = dynsm + KC;       // 8192: avg_probs partial
    __shared__ float sval[256];
    __shared__ int   sidx[256];
    __shared__ float ss[256], su[256], sm2[256];
    int tid = threadIdx.x;

    for (int k = tid; k < KC; k += 256) ap[k] = 0.f;

    for (int rr = 0; rr < 32; rr++) {
        int n = blockIdx.x * 32 + rr;
        const float* Grow = g_G + (size_t)n * KC;
        __syncthreads();

        float best = -INFINITY; int bidx = KC;
        for (int k = tid; k < KC; k += 256) {
            float l = (2.f * Grow[k] - g_c2[k]) * INV_T;
            sl[k] = l;
            if (l > best) { best = l; bidx = k; }
        }
        sval[tid] = best; sidx[tid] = bidx;
        __syncthreads();
        for (int off = 128; off; off >>= 1) {
            if (tid < off) {
                float ov = sval[tid + off]; int oi = sidx[tid + off];
                if (ov > sval[tid] || (ov == sval[tid] && oi < sidx[tid])) { sval[tid] = ov; sidx[tid] = oi; }
            }
            __syncthreads();
        }
        float m = sval[0]; int idx = sidx[0];

        float s = 0.f, u = 0.f, mx2 = -INFINITY;
        for (int k = tid; k < KC; k += 256) {
            float l = sl[k];
            float z = l - m;
            float e = __expf(z);
            s += e; u += z * e;
            if (k != idx && l > mx2) mx2 = l;
        }
        ss[tid] = s; su[tid] = u; sm2[tid] = mx2;
        __syncthreads();
        for (int off = 128; off; off >>= 1) {
            if (tid < off) {
                ss[tid] += ss[tid + off]; su[tid] += su[tid + off];
                if (sm2[tid + off] > sm2[tid]) sm2[tid] = sm2[tid + off];
            }
            __syncthreads();
        }
        float S = ss[0];
        float sinv = 1.f / S;
        if (tid == 0) {
            g_idx[n] = idx;
            atomicAdd(&g_plogp, su[0] * sinv - logf(S));
            if (m - sm2[0] < 0.05f) {
                int f = atomicAdd(&g_nflag, 1);
                g_flag[f] = n;
            }
        }
        for (int k = tid; k < KC; k += 256)
            ap[k] += __expf(sl[k] - m) * sinv;
    }
    __syncthreads();
    for (int k = tid; k < KC; k += 256)
        atomicAdd(&g_avgp[k], ap[k]);
}

// ---------------- exact fp32 argmin for flagged rows ----------------
__global__ __launch_bounds__(256) void refine_kernel(const float* __restrict__ x,
                                                     const float* __restrict__ cb) {
    __shared__ float xs[DD];
    __shared__ float rv[256];
    __shared__ int   ri[256];
    __shared__ float a2s;
    int tid = threadIdx.x;
    int nf = g_nflag;
    for (int f = blockIdx.x; f < nf; f += gridDim.x) {
        int n = g_flag[f];
        __syncthreads();
        xs[tid] = x[(size_t)n * DD + tid];
        rv[tid] = xs[tid] * xs[tid];
        __syncthreads();
        for (int off = 128; off; off >>= 1) {
            if (tid < off) rv[tid] += rv[tid + off];
            __syncthreads();
        }
        if (tid == 0) a2s = rv[0];
        __syncthreads();
        float a2 = a2s;

        float best = INFINITY; int bi = KC;
        for (int k = tid; k < KC; k += 256) {
            const float* c = cb + (size_t)k * DD;
            float dot = 0.f;
            #pragma unroll 8
            for (int d = 0; d < DD; d += 4) {
                float4 cc = *(const float4*)(c + d);
                dot += xs[d] * cc.x + xs[d+1] * cc.y + xs[d+2] * cc.z + xs[d+3] * cc.w;
            }
            float dist = (a2 - 2.f * dot) + g_c2[k];
            if (dist < best) { best = dist; bi = k; }
        }
        rv[tid] = best; ri[tid] = bi;
        __syncthreads();
        for (int off = 128; off; off >>= 1) {
            if (tid < off) {
                float ov = rv[tid + off]; int oi = ri[tid + off];
                if (ov < rv[tid] || (ov == rv[tid] && oi < ri[tid])) { rv[tid] = ov; ri[tid] = oi; }
            }
            __syncthreads();
        }
        if (tid == 0) g_idx[n] = ri[0];
        __syncthreads();
    }
}

// ---------------- avg entropy ----------------
__global__ __launch_bounds__(256) void avgent_kernel() {
    int i = blockIdx.x * blockDim.x + threadIdx.x;
    float ap = g_avgp[i] * (1.f / (float)NROWS);
    float h = -ap * logf(ap + 1e-5f);
    #pragma unroll
    for (int o = 16; o; o >>= 1) h += __shfl_down_sync(0xffffffff, h, o);
    __shared__ float sh[8];
    int wid = threadIdx.x >> 5, lid = threadIdx.x & 31;
    if (lid == 0) sh[wid] = h;
    __syncthreads();
    if (threadIdx.x == 0) {
        float t = 0.f;
        #pragma unroll
        for (int w = 0; w < 8; w++) t += sh[w];
        atomicAdd(&g_avgent, t);
    }
}

// ---------------- gather + MSE + indices ----------------
__global__ __launch_bounds__(256) void gather_kernel(const float* __restrict__ x,
                                                     const float* __restrict__ cb,
                                                     float* __restrict__ out) {
    int n = blockIdx.x, tid = threadIdx.x;
    int idx = g_idx[n];
    float q  = cb[(size_t)idx * DD + tid];
    float xv = x[(size_t)n * DD + tid];
    out[(size_t)n * DD + tid] = q;
    float d = q - xv;
    float sq = d * d;
    #pragma unroll
    for (int o = 16; o; o >>= 1) sq += __shfl_down_sync(0xffffffff, sq, o);
    __shared__ float sh[8];
    int wid = tid >> 5, lid = tid & 31;
    if (lid == 0) sh[wid] = sq;
    __syncthreads();
    if (tid == 0) {
        float t = 0.f;
        #pragma unroll
        for (int w = 0; w < 8; w++) t += sh[w];
        atomicAdd(&g_mse, t);
        out[(size_t)TOTAL_Q + 1 + n] = (float)idx;
    }
}

// ---------------- final loss ----------------
__global__ void final_kernel(float* __restrict__ out) {
    float mse_mean = g_mse / (float)TOTAL_Q;
    float sample_entropy = -g_plogp / (float)NROWS;
    float entropy_loss = sample_entropy - g_avgent;
    float loss = 1.25f * mse_mean + 0.1f * entropy_loss;
    out[TOTAL_Q] = loss;
}

extern "C" void kernel_launch(void* const* d_in, const int* in_sizes, int n_in,
                              void* d_out, int out_size) {
    const float* x  = (const float*)d_in[0];
    const float* cb = (const float*)d_in[1];
    float* out = (float*)d_out;

    cudaFuncSetAttribute(rowstats_kernel, cudaFuncAttributeMaxDynamicSharedMemorySize, 2 * KC * 4);

    init_kernel<<<32, 256>>>();
    c2_kernel<<<KC, 256>>>(cb);
    convert_kernel<<<TOTAL_Q / 1024, 256>>>(x, cb);
    mma_gemm_kernel<<<dim3(KC / BN, NROWS / BM), 256>>>();
    rowstats_kernel<<<NROWS / 32, 256, 2 * KC * 4>>>();
    refine_kernel<<<64, 256>>>(x, cb);
    avgent_kernel<<<KC / 256, 256>>>();
    gather_kernel<<<NROWS, 256>>>(x, cb, out);
    final_kernel<<<1, 1>>>(out);
}